// round 1
// baseline (speedup 1.0000x reference)
#include <cuda_runtime.h>
#include <cstdint>

// Problem constants
#define TOK   4096      // B*T
#define T_SEQ 2048
#define C_EMB 1024
#define NHEAD 16
#define HD    64
#define HID   2816

// ---------------- scratch (static device globals; no allocations) ----------
__device__ __align__(16) float g_h  [(size_t)TOK * C_EMB];
__device__ __align__(16) float g_qkv[(size_t)TOK * 3 * C_EMB];
__device__ __align__(16) float g_y  [(size_t)TOK * C_EMB];
__device__ __align__(16) float g_x2 [(size_t)TOK * C_EMB];
__device__ __align__(16) float g_fc1[(size_t)TOK * HID];
__device__ __align__(16) float g_fc2[(size_t)TOK * HID];

// ---------------- RMSNorm: one block per row, 256 threads -------------------
__global__ __launch_bounds__(256) void rmsnorm_k(const float* __restrict__ x,
                                                 const float* __restrict__ sc,
                                                 float* __restrict__ out) {
    int row = blockIdx.x;
    const float4* xr = (const float4*)(x + (size_t)row * C_EMB);
    float4 v = xr[threadIdx.x];                   // 256 * 4 = 1024 elems
    float ss = v.x * v.x + v.y * v.y + v.z * v.z + v.w * v.w;
    #pragma unroll
    for (int o = 16; o; o >>= 1) ss += __shfl_xor_sync(0xffffffffu, ss, o);
    __shared__ float red[8];
    int wid = threadIdx.x >> 5, lane = threadIdx.x & 31;
    if (lane == 0) red[wid] = ss;
    __syncthreads();
    if (wid == 0) {
        float t = (lane < 8) ? red[lane] : 0.f;
        #pragma unroll
        for (int o = 4; o; o >>= 1) t += __shfl_xor_sync(0xffffffffu, t, o);
        if (lane == 0) red[0] = t;
    }
    __syncthreads();
    float inv = rsqrtf(red[0] * (1.0f / C_EMB) + 1e-5f);
    float4 s4 = ((const float4*)sc)[threadIdx.x];
    float4 o4;
    o4.x = v.x * inv * s4.x;
    o4.y = v.y * inv * s4.y;
    o4.z = v.z * inv * s4.z;
    o4.w = v.w * inv * s4.w;
    ((float4*)(out + (size_t)row * C_EMB))[threadIdx.x] = o4;
}

// ---------------- SGEMM 128x128x8, 256 threads, 8x8 per thread -------------
// C[M,N] = A[M,K] @ B[K,N]  (+ R if non-null). All row-major.
// Requires M%128==0, N%128==0, K%8==0.
__global__ __launch_bounds__(256) void sgemm_k(const float* __restrict__ A,
                                               const float* __restrict__ B,
                                               float* __restrict__ C,
                                               const float* __restrict__ R,
                                               int M, int N, int K) {
    __shared__ float As[8][128];
    __shared__ float Bs[8][128];
    int bx = blockIdx.x;   // N tile
    int by = blockIdx.y;   // M tile
    int tid = threadIdx.x;

    int arow = tid >> 1;           // 0..127
    int acol = (tid & 1) * 4;      // 0 or 4
    int brow = tid >> 5;           // 0..7
    int bcol = (tid & 31) * 4;     // 0..124
    int trow = (tid >> 4) * 8;     // 0..120
    int tcol = (tid & 15) * 8;     // 0..120

    float acc[8][8];
    #pragma unroll
    for (int i = 0; i < 8; i++)
        #pragma unroll
        for (int j = 0; j < 8; j++) acc[i][j] = 0.f;

    const float* Aptr = A + (size_t)(by * 128 + arow) * K + acol;
    const float* Bptr = B + (size_t)brow * N + bx * 128 + bcol;

    for (int k0 = 0; k0 < K; k0 += 8) {
        float4 av = *(const float4*)(Aptr + k0);
        As[acol + 0][arow] = av.x;
        As[acol + 1][arow] = av.y;
        As[acol + 2][arow] = av.z;
        As[acol + 3][arow] = av.w;
        float4 bv = *(const float4*)(Bptr + (size_t)k0 * N);
        *(float4*)&Bs[brow][bcol] = bv;
        __syncthreads();
        #pragma unroll
        for (int kk = 0; kk < 8; kk++) {
            float4 a0 = *(const float4*)&As[kk][trow];
            float4 a1 = *(const float4*)&As[kk][trow + 4];
            float4 b0 = *(const float4*)&Bs[kk][tcol];
            float4 b1 = *(const float4*)&Bs[kk][tcol + 4];
            float ar[8] = {a0.x, a0.y, a0.z, a0.w, a1.x, a1.y, a1.z, a1.w};
            float br[8] = {b0.x, b0.y, b0.z, b0.w, b1.x, b1.y, b1.z, b1.w};
            #pragma unroll
            for (int i = 0; i < 8; i++)
                #pragma unroll
                for (int j = 0; j < 8; j++) acc[i][j] += ar[i] * br[j];
        }
        __syncthreads();
    }

    #pragma unroll
    for (int i = 0; i < 8; i++) {
        size_t r = (size_t)(by * 128 + trow + i);
        float* cp = C + r * N + bx * 128 + tcol;
        float4 o0 = make_float4(acc[i][0], acc[i][1], acc[i][2], acc[i][3]);
        float4 o1 = make_float4(acc[i][4], acc[i][5], acc[i][6], acc[i][7]);
        if (R) {
            const float4* rp = (const float4*)(R + r * N + bx * 128 + tcol);
            float4 r0 = rp[0], r1 = rp[1];
            o0.x += r0.x; o0.y += r0.y; o0.z += r0.z; o0.w += r0.w;
            o1.x += r1.x; o1.y += r1.y; o1.z += r1.z; o1.w += r1.w;
        }
        ((float4*)cp)[0] = o0;
        ((float4*)cp)[1] = o1;
    }
}

// ---------------- RoPE in place on q and k parts of g_qkv -------------------
__global__ __launch_bounds__(256) void rope_k(float* __restrict__ qkv) {
    int idx = blockIdx.x * 256 + threadIdx.x;   // 2 * 4096 * 16 * 32 = 2^22
    int p     = idx & 31;
    int h     = (idx >> 5) & 15;
    int tok   = (idx >> 9) & 4095;
    int which = idx >> 21;                      // 0 = q, 1 = k
    int t     = tok & 2047;                     // position within sequence
    size_t base = (size_t)tok * 3072 + (size_t)which * 1024 + h * 64 + 2 * p;
    float xe = qkv[base], xo = qkv[base + 1];
    float freq = powf(10000.0f, -(float)p / 32.0f);   // base^{-2p/64}
    float ang = (float)t * freq;
    float c = cosf(ang), s = sinf(ang);
    qkv[base]     = xe * c - xo * s;
    qkv[base + 1] = xe * s + xo * c;
}

// ---------------- Flash attention (fp32, online softmax) -------------------
// grid: (32 q-tiles, 16 heads, 2 batch); block 256.
// Q tile 64 rows; K/V tiles 32 rows. head dim 64.
__global__ __launch_bounds__(256) void flash_k(const float* __restrict__ qkv,
                                               const int* __restrict__ ymask,
                                               float* __restrict__ y) {
    __shared__ float Qs[64 * 68];
    __shared__ float Ks[32 * 65];
    __shared__ float Vs[32 * 68];
    __shared__ float Ps[64 * 33];
    __shared__ int   yms[64];

    int tid = threadIdx.x;
    int qt = blockIdx.x, h = blockIdx.y, b = blockIdx.z;
    int q0 = qt * 64;
    const float* base = qkv + (size_t)(b * T_SEQ) * 3072 + h * 64;

    // Q tile load (float4, coalesced)
    #pragma unroll
    for (int i = 0; i < 4; i++) {
        int e = tid + i * 256;            // 1024 float4
        int r = e >> 4;
        int c = (e & 15) * 4;
        float4 v = *(const float4*)(base + (size_t)(q0 + r) * 3072 + c);
        *(float4*)&Qs[r * 68 + c] = v;
    }
    if (tid < 64) yms[tid] = ymask[b * 64 + tid];

    int qi = tid >> 2;        // 0..63 (q row in tile)
    int g  = tid & 3;         // group of 4 threads per row
    int qg = q0 + qi;

    float m = -1e30f, l = 0.f;
    float acc[16];
    #pragma unroll
    for (int j = 0; j < 16; j++) acc[j] = 0.f;

    int nkt = qt * 2 + 2;     // K tiles covering causal range
    for (int kt = 0; kt < nkt; kt++) {
        __syncthreads();      // protect K/V/P from previous iteration readers
        #pragma unroll
        for (int i = 0; i < 8; i++) {
            int e = tid + i * 256;        // 2048 elems
            int r = e >> 6, c = e & 63;
            size_t go = (size_t)(kt * 32 + r) * 3072 + c;
            Ks[r * 65 + c] = base[go + 1024];
            Vs[r * 68 + c] = base[go + 2048];
        }
        __syncthreads();

        // scores: 8 k-columns per thread
        float s[8];
        #pragma unroll
        for (int jj = 0; jj < 8; jj++) s[jj] = 0.f;
        const float* qrow = &Qs[qi * 68];
        for (int d = 0; d < 64; d++) {
            float qv = qrow[d];
            #pragma unroll
            for (int jj = 0; jj < 8; jj++)
                s[jj] += qv * Ks[(g * 8 + jj) * 65 + d];
        }

        int k0 = kt * 32;
        float tmax = -1e30f;
        #pragma unroll
        for (int jj = 0; jj < 8; jj++) {
            int kg = k0 + g * 8 + jj;
            float sv = s[jj] * 0.125f;
            bool ok = (kg <= qg) ||
                      (qg < 64 && kg < 64 && yms[qg] && yms[kg]);
            sv = ok ? sv : -1e30f;
            s[jj] = sv;
            tmax = fmaxf(tmax, sv);
        }
        tmax = fmaxf(tmax, __shfl_xor_sync(0xffffffffu, tmax, 1));
        tmax = fmaxf(tmax, __shfl_xor_sync(0xffffffffu, tmax, 2));
        float mnew = fmaxf(m, tmax);
        float alpha = expf(m - mnew);
        float ssum = 0.f;
        #pragma unroll
        for (int jj = 0; jj < 8; jj++) {
            float p = expf(s[jj] - mnew);
            Ps[qi * 33 + g * 8 + jj] = p;
            ssum += p;
        }
        ssum += __shfl_xor_sync(0xffffffffu, ssum, 1);
        ssum += __shfl_xor_sync(0xffffffffu, ssum, 2);
        l = l * alpha + ssum;
        m = mnew;
        #pragma unroll
        for (int j = 0; j < 16; j++) acc[j] *= alpha;
        __syncthreads();

        // O += P @ V ; thread owns d = g*16 .. g*16+15
        #pragma unroll
        for (int kj = 0; kj < 32; kj++) {
            float pv = Ps[qi * 33 + kj];
            const float4* vr = (const float4*)&Vs[kj * 68 + g * 16];
            float4 v0 = vr[0], v1 = vr[1], v2 = vr[2], v3 = vr[3];
            acc[0]  += pv * v0.x; acc[1]  += pv * v0.y;
            acc[2]  += pv * v0.z; acc[3]  += pv * v0.w;
            acc[4]  += pv * v1.x; acc[5]  += pv * v1.y;
            acc[6]  += pv * v1.z; acc[7]  += pv * v1.w;
            acc[8]  += pv * v2.x; acc[9]  += pv * v2.y;
            acc[10] += pv * v2.z; acc[11] += pv * v2.w;
            acc[12] += pv * v3.x; acc[13] += pv * v3.y;
            acc[14] += pv * v3.z; acc[15] += pv * v3.w;
        }
    }

    float invl = 1.f / l;
    float* yo = y + (size_t)(b * T_SEQ + qg) * 1024 + h * 64 + g * 16;
    #pragma unroll
    for (int j = 0; j < 16; j += 4) {
        float4 o = make_float4(acc[j] * invl, acc[j + 1] * invl,
                               acc[j + 2] * invl, acc[j + 3] * invl);
        *(float4*)(yo + j) = o;
    }
}

// ---------------- SiLU(a) * b, in place into a ------------------------------
__global__ __launch_bounds__(256) void silu_mul_k(float* __restrict__ a,
                                                  const float* __restrict__ b,
                                                  int n4) {
    int i = blockIdx.x * 256 + threadIdx.x;
    if (i >= n4) return;
    float4 av = ((float4*)a)[i];
    float4 bv = ((const float4*)b)[i];
    av.x = av.x * bv.x / (1.f + expf(-av.x));
    av.y = av.y * bv.y / (1.f + expf(-av.y));
    av.z = av.z * bv.z / (1.f + expf(-av.z));
    av.w = av.w * bv.w / (1.f + expf(-av.w));
    ((float4*)a)[i] = av;
}

// ---------------- launch ----------------------------------------------------
extern "C" void kernel_launch(void* const* d_in, const int* in_sizes, int n_in,
                              void* d_out, int out_size) {
    const float* x    = (const float*)d_in[0];
    const int*   ym   = (const int*)  d_in[1];
    const float* Wqkv = (const float*)d_in[2];
    const float* Wap  = (const float*)d_in[3];
    const float* sc1  = (const float*)d_in[4];
    const float* sc2  = (const float*)d_in[5];
    const float* Wfc1 = (const float*)d_in[6];
    const float* Wfc2 = (const float*)d_in[7];
    const float* Wmp  = (const float*)d_in[8];
    float* out = (float*)d_out;

    float *h, *qkv, *y, *x2, *fc1, *fc2;
    cudaGetSymbolAddress((void**)&h,   g_h);
    cudaGetSymbolAddress((void**)&qkv, g_qkv);
    cudaGetSymbolAddress((void**)&y,   g_y);
    cudaGetSymbolAddress((void**)&x2,  g_x2);
    cudaGetSymbolAddress((void**)&fc1, g_fc1);
    cudaGetSymbolAddress((void**)&fc2, g_fc2);

    // 1) h = rmsnorm(x, scale1)
    rmsnorm_k<<<TOK, 256>>>(x, sc1, h);
    // 2) qkv = h @ Wqkv  [4096,3072]
    sgemm_k<<<dim3(3072 / 128, TOK / 128), 256>>>(h, Wqkv, qkv, nullptr,
                                                  TOK, 3072, C_EMB);
    // 3) RoPE in place on q,k
    rope_k<<<(1 << 22) / 256, 256>>>(qkv);
    // 4) attention -> y
    flash_k<<<dim3(T_SEQ / 64, NHEAD, 2), 256>>>(qkv, ym, y);
    // 5) x2 = x + y @ Wattn_proj
    sgemm_k<<<dim3(C_EMB / 128, TOK / 128), 256>>>(y, Wap, x2, x,
                                                   TOK, C_EMB, C_EMB);
    // 6) h = rmsnorm(x2, scale2)
    rmsnorm_k<<<TOK, 256>>>(x2, sc2, h);
    // 7) fc1 = h @ Wfc1 ; fc2 = h @ Wfc2
    sgemm_k<<<dim3(HID / 128, TOK / 128), 256>>>(h, Wfc1, fc1, nullptr,
                                                 TOK, HID, C_EMB);
    sgemm_k<<<dim3(HID / 128, TOK / 128), 256>>>(h, Wfc2, fc2, nullptr,
                                                 TOK, HID, C_EMB);
    // 8) fc1 = silu(fc1) * fc2
    int n4 = TOK * HID / 4;
    silu_mul_k<<<(n4 + 255) / 256, 256>>>(fc1, fc2, n4);
    // 9) out = x2 + fc1 @ Wmlp_proj
    sgemm_k<<<dim3(C_EMB / 128, TOK / 128), 256>>>(fc1, Wmp, out, x2,
                                                   TOK, C_EMB, HID);
}

// round 2
// speedup vs baseline: 1.6163x; 1.6163x over previous
#include <cuda_runtime.h>
#include <cstdint>

// Problem constants
#define TOK   4096      // B*T
#define T_SEQ 2048
#define C_EMB 1024
#define NHEAD 16
#define HD    64
#define HID   2816

// ---------------- scratch (static device globals; no allocations) ----------
__device__ __align__(16) float g_h  [(size_t)TOK * C_EMB];
__device__ __align__(16) float g_qkv[(size_t)TOK * 3 * C_EMB];
__device__ __align__(16) float g_y  [(size_t)TOK * C_EMB];
__device__ __align__(16) float g_x2 [(size_t)TOK * C_EMB];
__device__ __align__(16) float g_fc1[(size_t)TOK * HID];
__device__ __align__(16) float g_fc2[(size_t)TOK * HID];

// ---------------- helpers ---------------------------------------------------
__device__ __forceinline__ uint32_t f2tf(float f) {
    uint32_t u;
    asm("cvt.rna.tf32.f32 %0, %1;" : "=r"(u) : "f"(f));
    return u;
}

__device__ __forceinline__ void mma_tf32(float* d, const uint32_t* a,
                                         const uint32_t* b) {
    asm volatile(
        "mma.sync.aligned.m16n8k8.row.col.f32.tf32.tf32.f32 "
        "{%0,%1,%2,%3}, {%4,%5,%6,%7}, {%8,%9}, {%0,%1,%2,%3};\n"
        : "+f"(d[0]), "+f"(d[1]), "+f"(d[2]), "+f"(d[3])
        : "r"(a[0]), "r"(a[1]), "r"(a[2]), "r"(a[3]), "r"(b[0]), "r"(b[1]));
}

__device__ __forceinline__ void cp_async16(void* smem, const void* gmem) {
    uint32_t s = (uint32_t)__cvta_generic_to_shared(smem);
    asm volatile("cp.async.ca.shared.global [%0], [%1], 16;\n"
                 :: "r"(s), "l"(gmem));
}

// ---------------- RMSNorm: one block per row, 256 threads -------------------
__global__ __launch_bounds__(256) void rmsnorm_k(const float* __restrict__ x,
                                                 const float* __restrict__ sc,
                                                 float* __restrict__ out) {
    int row = blockIdx.x;
    const float4* xr = (const float4*)(x + (size_t)row * C_EMB);
    float4 v = xr[threadIdx.x];
    float ss = v.x * v.x + v.y * v.y + v.z * v.z + v.w * v.w;
    #pragma unroll
    for (int o = 16; o; o >>= 1) ss += __shfl_xor_sync(0xffffffffu, ss, o);
    __shared__ float red[8];
    int wid = threadIdx.x >> 5, lane = threadIdx.x & 31;
    if (lane == 0) red[wid] = ss;
    __syncthreads();
    if (wid == 0) {
        float t = (lane < 8) ? red[lane] : 0.f;
        #pragma unroll
        for (int o = 4; o; o >>= 1) t += __shfl_xor_sync(0xffffffffu, t, o);
        if (lane == 0) red[0] = t;
    }
    __syncthreads();
    float inv = rsqrtf(red[0] * (1.0f / C_EMB) + 1e-5f);
    float4 s4 = ((const float4*)sc)[threadIdx.x];
    float4 o4;
    o4.x = v.x * inv * s4.x;
    o4.y = v.y * inv * s4.y;
    o4.z = v.z * inv * s4.z;
    o4.w = v.w * inv * s4.w;
    ((float4*)(out + (size_t)row * C_EMB))[threadIdx.x] = o4;
}

// ---------------- TF32 tensor-core GEMM -------------------------------------
// C[M,N] = A[M,K] @ B[K,N] (+ R). Row-major. M%128==0, N%128==0, K%16==0.
// Block 128x128, K-tile 16, 8 warps each computing 64x32, cp.async dbl-buffer.
#define AS_STRIDE 20    // 16 + 4 pad  -> conflict-free A fragment loads
#define BS_STRIDE 136   // 128 + 8 pad -> conflict-free B fragment loads

__global__ __launch_bounds__(256) void tf32gemm_k(const float* __restrict__ A,
                                                  const float* __restrict__ B,
                                                  float* __restrict__ C,
                                                  const float* __restrict__ R,
                                                  int M, int N, int K) {
    __shared__ float As[2][128 * AS_STRIDE];
    __shared__ float Bs[2][16 * BS_STRIDE];

    int tid  = threadIdx.x;
    int wid  = tid >> 5;
    int lane = tid & 31;
    int g = lane >> 2;        // 0..7
    int q = lane & 3;         // 0..3
    int wm = (wid >> 2) * 64; // warp m offset: 0 or 64
    int wn = (wid & 3) * 32;  // warp n offset: 0,32,64,96
    int bx = blockIdx.x * 128;
    int by = blockIdx.y * 128;

    // global load coords
    int a_row = tid >> 2;           // 0..63 (plus +64 for second load)
    int a_col = (tid & 3) * 4;      // 0,4,8,12
    int b_row = tid >> 5;           // 0..7  (plus +8)
    int b_col = (tid & 31) * 4;     // 0..124

    const float* Agp = A + (size_t)(by + a_row) * K + a_col;
    const float* Bgp = B + (size_t)b_row * N + bx + b_col;

    float acc[4][4][4];
    #pragma unroll
    for (int i = 0; i < 4; i++)
        #pragma unroll
        for (int j = 0; j < 4; j++)
            #pragma unroll
            for (int e = 0; e < 4; e++) acc[i][j][e] = 0.f;

    auto load_tile = [&](int buf, int k0) {
        cp_async16(&As[buf][a_row * AS_STRIDE + a_col], Agp + k0);
        cp_async16(&As[buf][(a_row + 64) * AS_STRIDE + a_col],
                   Agp + k0 + (size_t)64 * K);
        cp_async16(&Bs[buf][b_row * BS_STRIDE + b_col],
                   Bgp + (size_t)k0 * N);
        cp_async16(&Bs[buf][(b_row + 8) * BS_STRIDE + b_col],
                   Bgp + (size_t)(k0 + 8) * N);
        asm volatile("cp.async.commit_group;\n");
    };

    load_tile(0, 0);
    asm volatile("cp.async.wait_group 0;\n");
    __syncthreads();

    int KT = K >> 4;
    for (int kt = 0; kt < KT; kt++) {
        int buf = kt & 1;
        if (kt + 1 < KT) load_tile(buf ^ 1, (kt + 1) << 4);

        #pragma unroll
        for (int ks = 0; ks < 2; ks++) {
            uint32_t afr[4][4], bfr[4][2];
            #pragma unroll
            for (int mt = 0; mt < 4; mt++) {
                int r = wm + 16 * mt + g;
                const float* ap = &As[buf][r * AS_STRIDE + ks * 8 + q];
                afr[mt][0] = f2tf(ap[0]);
                afr[mt][1] = f2tf(ap[8 * AS_STRIDE]);
                afr[mt][2] = f2tf(ap[4]);
                afr[mt][3] = f2tf(ap[8 * AS_STRIDE + 4]);
            }
            #pragma unroll
            for (int nt = 0; nt < 4; nt++) {
                int c = wn + 8 * nt + g;
                const float* bp = &Bs[buf][(ks * 8 + q) * BS_STRIDE + c];
                bfr[nt][0] = f2tf(bp[0]);
                bfr[nt][1] = f2tf(bp[4 * BS_STRIDE]);
            }
            #pragma unroll
            for (int mt = 0; mt < 4; mt++)
                #pragma unroll
                for (int nt = 0; nt < 4; nt++)
                    mma_tf32(acc[mt][nt], afr[mt], bfr[nt]);
        }

        asm volatile("cp.async.wait_group 0;\n");
        __syncthreads();
    }

    // epilogue
    #pragma unroll
    for (int mt = 0; mt < 4; mt++) {
        #pragma unroll
        for (int nt = 0; nt < 4; nt++) {
            int r0 = by + wm + 16 * mt + g;
            int c0 = bx + wn + 8 * nt + 2 * q;
            float2 v0 = make_float2(acc[mt][nt][0], acc[mt][nt][1]);
            float2 v1 = make_float2(acc[mt][nt][2], acc[mt][nt][3]);
            if (R) {
                float2 r0v = *(const float2*)(R + (size_t)r0 * N + c0);
                float2 r1v = *(const float2*)(R + (size_t)(r0 + 8) * N + c0);
                v0.x += r0v.x; v0.y += r0v.y;
                v1.x += r1v.x; v1.y += r1v.y;
            }
            *(float2*)(C + (size_t)r0 * N + c0) = v0;
            *(float2*)(C + (size_t)(r0 + 8) * N + c0) = v1;
        }
    }
}

// ---------------- RoPE in place on q and k parts of g_qkv -------------------
__global__ __launch_bounds__(256) void rope_k(float* __restrict__ qkv) {
    int idx = blockIdx.x * 256 + threadIdx.x;
    int p     = idx & 31;
    int h     = (idx >> 5) & 15;
    int tok   = (idx >> 9) & 4095;
    int which = idx >> 21;                      // 0 = q, 1 = k
    int t     = tok & 2047;
    size_t base = (size_t)tok * 3072 + (size_t)which * 1024 + h * 64 + 2 * p;
    float xe = qkv[base], xo = qkv[base + 1];
    float freq = powf(10000.0f, -(float)p / 32.0f);
    float ang = (float)t * freq;
    float c = cosf(ang), s = sinf(ang);
    qkv[base]     = xe * c - xo * s;
    qkv[base + 1] = xe * s + xo * c;
}

// ---------------- Flash attention (fp32, online softmax) -------------------
__global__ __launch_bounds__(256) void flash_k(const float* __restrict__ qkv,
                                               const int* __restrict__ ymask,
                                               float* __restrict__ y) {
    __shared__ float Qs[64 * 68];
    __shared__ float Ks[32 * 65];
    __shared__ float Vs[32 * 68];
    __shared__ float Ps[64 * 33];
    __shared__ int   yms[64];

    int tid = threadIdx.x;
    int qt = blockIdx.x, h = blockIdx.y, b = blockIdx.z;
    int q0 = qt * 64;
    const float* base = qkv + (size_t)(b * T_SEQ) * 3072 + h * 64;

    #pragma unroll
    for (int i = 0; i < 4; i++) {
        int e = tid + i * 256;
        int r = e >> 4;
        int c = (e & 15) * 4;
        float4 v = *(const float4*)(base + (size_t)(q0 + r) * 3072 + c);
        *(float4*)&Qs[r * 68 + c] = v;
    }
    if (tid < 64) yms[tid] = ymask[b * 64 + tid];

    int qi = tid >> 2;
    int g  = tid & 3;
    int qg = q0 + qi;

    float m = -1e30f, l = 0.f;
    float acc[16];
    #pragma unroll
    for (int j = 0; j < 16; j++) acc[j] = 0.f;

    int nkt = qt * 2 + 2;
    for (int kt = 0; kt < nkt; kt++) {
        __syncthreads();
        #pragma unroll
        for (int i = 0; i < 8; i++) {
            int e = tid + i * 256;
            int r = e >> 6, c = e & 63;
            size_t go = (size_t)(kt * 32 + r) * 3072 + c;
            Ks[r * 65 + c] = base[go + 1024];
            Vs[r * 68 + c] = base[go + 2048];
        }
        __syncthreads();

        float s[8];
        #pragma unroll
        for (int jj = 0; jj < 8; jj++) s[jj] = 0.f;
        const float* qrow = &Qs[qi * 68];
        for (int d = 0; d < 64; d++) {
            float qv = qrow[d];
            #pragma unroll
            for (int jj = 0; jj < 8; jj++)
                s[jj] += qv * Ks[(g * 8 + jj) * 65 + d];
        }

        int k0 = kt * 32;
        float tmax = -1e30f;
        #pragma unroll
        for (int jj = 0; jj < 8; jj++) {
            int kg = k0 + g * 8 + jj;
            float sv = s[jj] * 0.125f;
            bool ok = (kg <= qg) ||
                      (qg < 64 && kg < 64 && yms[qg] && yms[kg]);
            sv = ok ? sv : -1e30f;
            s[jj] = sv;
            tmax = fmaxf(tmax, sv);
        }
        tmax = fmaxf(tmax, __shfl_xor_sync(0xffffffffu, tmax, 1));
        tmax = fmaxf(tmax, __shfl_xor_sync(0xffffffffu, tmax, 2));
        float mnew = fmaxf(m, tmax);
        float alpha = expf(m - mnew);
        float ssum = 0.f;
        #pragma unroll
        for (int jj = 0; jj < 8; jj++) {
            float p = expf(s[jj] - mnew);
            Ps[qi * 33 + g * 8 + jj] = p;
            ssum += p;
        }
        ssum += __shfl_xor_sync(0xffffffffu, ssum, 1);
        ssum += __shfl_xor_sync(0xffffffffu, ssum, 2);
        l = l * alpha + ssum;
        m = mnew;
        #pragma unroll
        for (int j = 0; j < 16; j++) acc[j] *= alpha;
        __syncthreads();

        #pragma unroll
        for (int kj = 0; kj < 32; kj++) {
            float pv = Ps[qi * 33 + kj];
            const float4* vr = (const float4*)&Vs[kj * 68 + g * 16];
            float4 v0 = vr[0], v1 = vr[1], v2 = vr[2], v3 = vr[3];
            acc[0]  += pv * v0.x; acc[1]  += pv * v0.y;
            acc[2]  += pv * v0.z; acc[3]  += pv * v0.w;
            acc[4]  += pv * v1.x; acc[5]  += pv * v1.y;
            acc[6]  += pv * v1.z; acc[7]  += pv * v1.w;
            acc[8]  += pv * v2.x; acc[9]  += pv * v2.y;
            acc[10] += pv * v2.z; acc[11] += pv * v2.w;
            acc[12] += pv * v3.x; acc[13] += pv * v3.y;
            acc[14] += pv * v3.z; acc[15] += pv * v3.w;
        }
    }

    float invl = 1.f / l;
    float* yo = y + (size_t)(b * T_SEQ + qg) * 1024 + h * 64 + g * 16;
    #pragma unroll
    for (int j = 0; j < 16; j += 4) {
        float4 o = make_float4(acc[j] * invl, acc[j + 1] * invl,
                               acc[j + 2] * invl, acc[j + 3] * invl);
        *(float4*)(yo + j) = o;
    }
}

// ---------------- SiLU(a) * b, in place into a ------------------------------
__global__ __launch_bounds__(256) void silu_mul_k(float* __restrict__ a,
                                                  const float* __restrict__ b,
                                                  int n4) {
    int i = blockIdx.x * 256 + threadIdx.x;
    if (i >= n4) return;
    float4 av = ((float4*)a)[i];
    float4 bv = ((const float4*)b)[i];
    av.x = av.x * bv.x / (1.f + expf(-av.x));
    av.y = av.y * bv.y / (1.f + expf(-av.y));
    av.z = av.z * bv.z / (1.f + expf(-av.z));
    av.w = av.w * bv.w / (1.f + expf(-av.w));
    ((float4*)a)[i] = av;
}

// ---------------- launch ----------------------------------------------------
extern "C" void kernel_launch(void* const* d_in, const int* in_sizes, int n_in,
                              void* d_out, int out_size) {
    const float* x    = (const float*)d_in[0];
    const int*   ym   = (const int*)  d_in[1];
    const float* Wqkv = (const float*)d_in[2];
    const float* Wap  = (const float*)d_in[3];
    const float* sc1  = (const float*)d_in[4];
    const float* sc2  = (const float*)d_in[5];
    const float* Wfc1 = (const float*)d_in[6];
    const float* Wfc2 = (const float*)d_in[7];
    const float* Wmp  = (const float*)d_in[8];
    float* out = (float*)d_out;

    float *h, *qkv, *y, *x2, *fc1, *fc2;
    cudaGetSymbolAddress((void**)&h,   g_h);
    cudaGetSymbolAddress((void**)&qkv, g_qkv);
    cudaGetSymbolAddress((void**)&y,   g_y);
    cudaGetSymbolAddress((void**)&x2,  g_x2);
    cudaGetSymbolAddress((void**)&fc1, g_fc1);
    cudaGetSymbolAddress((void**)&fc2, g_fc2);

    // 1) h = rmsnorm(x, scale1)
    rmsnorm_k<<<TOK, 256>>>(x, sc1, h);
    // 2) qkv = h @ Wqkv  [4096,3072]
    tf32gemm_k<<<dim3(3072 / 128, TOK / 128), 256>>>(h, Wqkv, qkv, nullptr,
                                                     TOK, 3072, C_EMB);
    // 3) RoPE in place on q,k
    rope_k<<<(1 << 22) / 256, 256>>>(qkv);
    // 4) attention -> y
    flash_k<<<dim3(T_SEQ / 64, NHEAD, 2), 256>>>(qkv, ym, y);
    // 5) x2 = x + y @ Wattn_proj
    tf32gemm_k<<<dim3(C_EMB / 128, TOK / 128), 256>>>(y, Wap, x2, x,
                                                      TOK, C_EMB, C_EMB);
    // 6) h = rmsnorm(x2, scale2)
    rmsnorm_k<<<TOK, 256>>>(x2, sc2, h);
    // 7) fc1 = h @ Wfc1 ; fc2 = h @ Wfc2
    tf32gemm_k<<<dim3(HID / 128, TOK / 128), 256>>>(h, Wfc1, fc1, nullptr,
                                                    TOK, HID, C_EMB);
    tf32gemm_k<<<dim3(HID / 128, TOK / 128), 256>>>(h, Wfc2, fc2, nullptr,
                                                    TOK, HID, C_EMB);
    // 8) fc1 = silu(fc1) * fc2
    int n4 = TOK * HID / 4;
    silu_mul_k<<<(n4 + 255) / 256, 256>>>(fc1, fc2, n4);
    // 9) out = x2 + fc1 @ Wmlp_proj
    tf32gemm_k<<<dim3(C_EMB / 128, TOK / 128), 256>>>(fc1, Wmp, out, x2,
                                                      TOK, C_EMB, HID);
}

// round 4
// speedup vs baseline: 3.8035x; 2.3532x over previous
#include <cuda_runtime.h>
#include <cstdint>

// Problem constants
#define TOK   4096      // B*T
#define T_SEQ 2048
#define C_EMB 1024
#define NHEAD 16
#define HD    64
#define HID   2816

// ---------------- scratch (static device globals; no allocations) ----------
__device__ __align__(16) float g_h  [(size_t)TOK * C_EMB];
__device__ __align__(16) float g_qkv[(size_t)TOK * 3 * C_EMB];
__device__ __align__(16) float g_y  [(size_t)TOK * C_EMB];
__device__ __align__(16) float g_x2 [(size_t)TOK * C_EMB];
__device__ __align__(16) float g_fc1[(size_t)TOK * HID];
__device__ __align__(16) float g_fc2[(size_t)TOK * HID];

// ---------------- helpers ---------------------------------------------------
__device__ __forceinline__ uint32_t f2tf(float f) {
    uint32_t u;
    asm("cvt.rna.tf32.f32 %0, %1;" : "=r"(u) : "f"(f));
    return u;
}

__device__ __forceinline__ void mma_tf32(float* d, const uint32_t* a,
                                         const uint32_t* b) {
    asm volatile(
        "mma.sync.aligned.m16n8k8.row.col.f32.tf32.tf32.f32 "
        "{%0,%1,%2,%3}, {%4,%5,%6,%7}, {%8,%9}, {%0,%1,%2,%3};\n"
        : "+f"(d[0]), "+f"(d[1]), "+f"(d[2]), "+f"(d[3])
        : "r"(a[0]), "r"(a[1]), "r"(a[2]), "r"(a[3]), "r"(b[0]), "r"(b[1]));
}

__device__ __forceinline__ void cp_async16(void* smem, const void* gmem) {
    uint32_t s = (uint32_t)__cvta_generic_to_shared(smem);
    asm volatile("cp.async.ca.shared.global [%0], [%1], 16;\n"
                 :: "r"(s), "l"(gmem));
}

// ---------------- RMSNorm: one block per row, 256 threads -------------------
__global__ __launch_bounds__(256) void rmsnorm_k(const float* __restrict__ x,
                                                 const float* __restrict__ sc,
                                                 float* __restrict__ out) {
    int row = blockIdx.x;
    const float4* xr = (const float4*)(x + (size_t)row * C_EMB);
    float4 v = xr[threadIdx.x];
    float ss = v.x * v.x + v.y * v.y + v.z * v.z + v.w * v.w;
    #pragma unroll
    for (int o = 16; o; o >>= 1) ss += __shfl_xor_sync(0xffffffffu, ss, o);
    __shared__ float red[8];
    int wid = threadIdx.x >> 5, lane = threadIdx.x & 31;
    if (lane == 0) red[wid] = ss;
    __syncthreads();
    if (wid == 0) {
        float t = (lane < 8) ? red[lane] : 0.f;
        #pragma unroll
        for (int o = 4; o; o >>= 1) t += __shfl_xor_sync(0xffffffffu, t, o);
        if (lane == 0) red[0] = t;
    }
    __syncthreads();
    float inv = rsqrtf(red[0] * (1.0f / C_EMB) + 1e-5f);
    float4 s4 = ((const float4*)sc)[threadIdx.x];
    float4 o4;
    o4.x = v.x * inv * s4.x;
    o4.y = v.y * inv * s4.y;
    o4.z = v.z * inv * s4.z;
    o4.w = v.w * inv * s4.w;
    ((float4*)(out + (size_t)row * C_EMB))[threadIdx.x] = o4;
}

// ---------------- TF32 tensor-core GEMM -------------------------------------
#define AS_STRIDE 20
#define BS_STRIDE 136

__global__ __launch_bounds__(256) void tf32gemm_k(const float* __restrict__ A,
                                                  const float* __restrict__ B,
                                                  float* __restrict__ C,
                                                  const float* __restrict__ R,
                                                  int M, int N, int K) {
    __shared__ float As[2][128 * AS_STRIDE];
    __shared__ float Bs[2][16 * BS_STRIDE];

    int tid  = threadIdx.x;
    int wid  = tid >> 5;
    int lane = tid & 31;
    int g = lane >> 2;
    int q = lane & 3;
    int wm = (wid >> 2) * 64;
    int wn = (wid & 3) * 32;
    int bx = blockIdx.x * 128;
    int by = blockIdx.y * 128;

    int a_row = tid >> 2;
    int a_col = (tid & 3) * 4;
    int b_row = tid >> 5;
    int b_col = (tid & 31) * 4;

    const float* Agp = A + (size_t)(by + a_row) * K + a_col;
    const float* Bgp = B + (size_t)b_row * N + bx + b_col;

    float acc[4][4][4];
    #pragma unroll
    for (int i = 0; i < 4; i++)
        #pragma unroll
        for (int j = 0; j < 4; j++)
            #pragma unroll
            for (int e = 0; e < 4; e++) acc[i][j][e] = 0.f;

    auto load_tile = [&](int buf, int k0) {
        cp_async16(&As[buf][a_row * AS_STRIDE + a_col], Agp + k0);
        cp_async16(&As[buf][(a_row + 64) * AS_STRIDE + a_col],
                   Agp + k0 + (size_t)64 * K);
        cp_async16(&Bs[buf][b_row * BS_STRIDE + b_col],
                   Bgp + (size_t)k0 * N);
        cp_async16(&Bs[buf][(b_row + 8) * BS_STRIDE + b_col],
                   Bgp + (size_t)(k0 + 8) * N);
        asm volatile("cp.async.commit_group;\n");
    };

    load_tile(0, 0);
    asm volatile("cp.async.wait_group 0;\n");
    __syncthreads();

    int KT = K >> 4;
    for (int kt = 0; kt < KT; kt++) {
        int buf = kt & 1;
        if (kt + 1 < KT) load_tile(buf ^ 1, (kt + 1) << 4);

        #pragma unroll
        for (int ks = 0; ks < 2; ks++) {
            uint32_t afr[4][4], bfr[4][2];
            #pragma unroll
            for (int mt = 0; mt < 4; mt++) {
                int r = wm + 16 * mt + g;
                const float* ap = &As[buf][r * AS_STRIDE + ks * 8 + q];
                afr[mt][0] = f2tf(ap[0]);
                afr[mt][1] = f2tf(ap[8 * AS_STRIDE]);
                afr[mt][2] = f2tf(ap[4]);
                afr[mt][3] = f2tf(ap[8 * AS_STRIDE + 4]);
            }
            #pragma unroll
            for (int nt = 0; nt < 4; nt++) {
                int c = wn + 8 * nt + g;
                const float* bp = &Bs[buf][(ks * 8 + q) * BS_STRIDE + c];
                bfr[nt][0] = f2tf(bp[0]);
                bfr[nt][1] = f2tf(bp[4 * BS_STRIDE]);
            }
            #pragma unroll
            for (int mt = 0; mt < 4; mt++)
                #pragma unroll
                for (int nt = 0; nt < 4; nt++)
                    mma_tf32(acc[mt][nt], afr[mt], bfr[nt]);
        }

        asm volatile("cp.async.wait_group 0;\n");
        __syncthreads();
    }

    #pragma unroll
    for (int mt = 0; mt < 4; mt++) {
        #pragma unroll
        for (int nt = 0; nt < 4; nt++) {
            int r0 = by + wm + 16 * mt + g;
            int c0 = bx + wn + 8 * nt + 2 * q;
            float2 v0 = make_float2(acc[mt][nt][0], acc[mt][nt][1]);
            float2 v1 = make_float2(acc[mt][nt][2], acc[mt][nt][3]);
            if (R) {
                float2 r0v = *(const float2*)(R + (size_t)r0 * N + c0);
                float2 r1v = *(const float2*)(R + (size_t)(r0 + 8) * N + c0);
                v0.x += r0v.x; v0.y += r0v.y;
                v1.x += r1v.x; v1.y += r1v.y;
            }
            *(float2*)(C + (size_t)r0 * N + c0) = v0;
            *(float2*)(C + (size_t)(r0 + 8) * N + c0) = v1;
        }
    }
}

// ---------------- RoPE in place on q and k parts of g_qkv -------------------
__global__ __launch_bounds__(256) void rope_k(float* __restrict__ qkv) {
    int idx = blockIdx.x * 256 + threadIdx.x;
    int p     = idx & 31;
    int h     = (idx >> 5) & 15;
    int tok   = (idx >> 9) & 4095;
    int which = idx >> 21;
    int t     = tok & 2047;
    size_t base = (size_t)tok * 3072 + (size_t)which * 1024 + h * 64 + 2 * p;
    float xe = qkv[base], xo = qkv[base + 1];
    float freq = powf(10000.0f, -(float)p / 32.0f);
    float ang = (float)t * freq;
    float c = cosf(ang), s = sinf(ang);
    qkv[base]     = xe * c - xo * s;
    qkv[base + 1] = xe * s + xo * c;
}

// ---------------- Flash attention with TF32 tensor cores -------------------
// Q tile 128, KV tile 64. 8 warps, warp w owns q-rows [16w,16w+16), all 64 kv.
// QK^T in 3xTF32 (hi/lo split); PV in 1x tf32. fp32 online softmax.
#define FST 68   // stride for Q/K/P smem
#define VST 72   // stride for V smem
#define BQ 128
#define BK 64

__global__ __launch_bounds__(256) void flash_mma_k(const float* __restrict__ qkv,
                                                   const int* __restrict__ ymask,
                                                   float* __restrict__ y) {
    extern __shared__ uint32_t dyn[];
    uint32_t* Qhi = dyn;                   // 128*68
    uint32_t* Qlo = Qhi + BQ * FST;        // 128*68
    uint32_t* Khi = Qlo + BQ * FST;        // 64*68
    uint32_t* Klo = Khi + BK * FST;        // 64*68
    uint32_t* Ps  = Klo + BK * FST;        // 128*68
    uint32_t* Vs  = Ps  + BQ * FST;        // 64*72
    __shared__ int yms[64];

    int tid = threadIdx.x;
    int w = tid >> 5, lane = tid & 31;
    int g = lane >> 2, q = lane & 3;
    int qt = gridDim.x - 1 - blockIdx.x;   // long blocks first
    int h = blockIdx.y, b = blockIdx.z;
    int q0 = qt * BQ;
    const float* base = qkv + (size_t)(b * T_SEQ) * 3072 + h * 64;

    // ---- load + split-convert Q tile ----
    #pragma unroll
    for (int i = 0; i < 8; i++) {
        int e = tid + i * 256;             // 2048 float4
        int r = e >> 4;
        int c = (e & 15) * 4;
        float4 v = *(const float4*)(base + (size_t)(q0 + r) * 3072 + c);
        int o = r * FST + c;
        float f[4] = {v.x, v.y, v.z, v.w};
        #pragma unroll
        for (int j = 0; j < 4; j++) {
            uint32_t hi = f2tf(f[j]);
            Qhi[o + j] = hi;
            Qlo[o + j] = f2tf(f[j] - __uint_as_float(hi));
        }
    }
    if (tid < 64) yms[tid] = ymask[b * 64 + tid];
    __syncthreads();

    int wr = w * 16;
    float o_acc[8][4];
    #pragma unroll
    for (int nt = 0; nt < 8; nt++)
        #pragma unroll
        for (int e = 0; e < 4; e++) o_acc[nt][e] = 0.f;
    float m0 = -1e30f, m1 = -1e30f, l0 = 0.f, l1 = 0.f;

    int rg0 = q0 + wr + g, rg1 = rg0 + 8;
    int nkt = 2 * qt + 2;

    for (int kt = 0; kt < nkt; kt++) {
        int k0 = kt * BK;
        // ---- load K (hi/lo) and V (tf32) tiles ----
        #pragma unroll
        for (int i = 0; i < 4; i++) {
            int e = tid + i * 256;         // 1024 float4
            int r = e >> 4;
            int c = (e & 15) * 4;
            const float* gsrc = base + (size_t)(k0 + r) * 3072 + c;
            float4 kv4 = *(const float4*)(gsrc + 1024);
            float4 vv4 = *(const float4*)(gsrc + 2048);
            int ok = r * FST + c;
            int ov = r * VST + c;
            float kf[4] = {kv4.x, kv4.y, kv4.z, kv4.w};
            float vf[4] = {vv4.x, vv4.y, vv4.z, vv4.w};
            #pragma unroll
            for (int j = 0; j < 4; j++) {
                uint32_t hi = f2tf(kf[j]);
                Khi[ok + j] = hi;
                Klo[ok + j] = f2tf(kf[j] - __uint_as_float(hi));
                Vs[ov + j] = f2tf(vf[j]);
            }
        }
        __syncthreads();

        bool active = (k0 <= q0 + wr + 15);
        if (active) {
            // ---- S = Q @ K^T (3xTF32) ----
            float s[8][4];
            #pragma unroll
            for (int nt = 0; nt < 8; nt++)
                #pragma unroll
                for (int e = 0; e < 4; e++) s[nt][e] = 0.f;

            #pragma unroll
            for (int ks = 0; ks < 8; ks++) {
                int ac = ks * 8 + q;
                uint32_t ah[4], al[4];
                ah[0] = Qhi[(wr + g) * FST + ac];
                ah[1] = Qhi[(wr + g + 8) * FST + ac];
                ah[2] = Qhi[(wr + g) * FST + ac + 4];
                ah[3] = Qhi[(wr + g + 8) * FST + ac + 4];
                al[0] = Qlo[(wr + g) * FST + ac];
                al[1] = Qlo[(wr + g + 8) * FST + ac];
                al[2] = Qlo[(wr + g) * FST + ac + 4];
                al[3] = Qlo[(wr + g + 8) * FST + ac + 4];
                #pragma unroll
                for (int nt = 0; nt < 8; nt++) {
                    int br = (nt * 8 + g) * FST + ac;
                    uint32_t bh[2] = {Khi[br], Khi[br + 4]};
                    uint32_t bl[2] = {Klo[br], Klo[br + 4]};
                    mma_tf32(s[nt], ah, bh);
                    mma_tf32(s[nt], al, bh);
                    mma_tf32(s[nt], ah, bl);
                }
            }

            // ---- mask + online softmax ----
            bool needmask = (k0 + BK - 1 > q0 + wr);
            bool istext = (q0 == 0) && (k0 == 0);
            float rm0 = -1e30f, rm1 = -1e30f;
            #pragma unroll
            for (int nt = 0; nt < 8; nt++) {
                #pragma unroll
                for (int e = 0; e < 4; e++) {
                    float sv = s[nt][e] * 0.125f;
                    if (needmask) {
                        int row = (e >= 2) ? rg1 : rg0;
                        int kg = k0 + nt * 8 + 2 * q + (e & 1);
                        bool ok = (kg <= row);
                        if (istext)
                            ok = ok || (row < 64 && kg < 64 && yms[row] && yms[kg]);
                        sv = ok ? sv : -1e30f;
                    }
                    s[nt][e] = sv;
                    if (e < 2) rm0 = fmaxf(rm0, sv);
                    else       rm1 = fmaxf(rm1, sv);
                }
            }
            rm0 = fmaxf(rm0, __shfl_xor_sync(0xffffffffu, rm0, 1));
            rm0 = fmaxf(rm0, __shfl_xor_sync(0xffffffffu, rm0, 2));
            rm1 = fmaxf(rm1, __shfl_xor_sync(0xffffffffu, rm1, 1));
            rm1 = fmaxf(rm1, __shfl_xor_sync(0xffffffffu, rm1, 2));

            float mn0 = fmaxf(m0, rm0), mn1 = fmaxf(m1, rm1);
            float a0 = __expf(m0 - mn0), a1 = __expf(m1 - mn1);
            float rl0 = 0.f, rl1 = 0.f;
            #pragma unroll
            for (int nt = 0; nt < 8; nt++) {
                float p0 = __expf(s[nt][0] - mn0);
                float p1 = __expf(s[nt][1] - mn0);
                float p2 = __expf(s[nt][2] - mn1);
                float p3 = __expf(s[nt][3] - mn1);
                rl0 += p0 + p1;
                rl1 += p2 + p3;
                int pc = nt * 8 + 2 * q;
                *(uint2*)&Ps[(wr + g) * FST + pc]     = make_uint2(f2tf(p0), f2tf(p1));
                *(uint2*)&Ps[(wr + g + 8) * FST + pc] = make_uint2(f2tf(p2), f2tf(p3));
                o_acc[nt][0] *= a0; o_acc[nt][1] *= a0;
                o_acc[nt][2] *= a1; o_acc[nt][3] *= a1;
            }
            rl0 += __shfl_xor_sync(0xffffffffu, rl0, 1);
            rl0 += __shfl_xor_sync(0xffffffffu, rl0, 2);
            rl1 += __shfl_xor_sync(0xffffffffu, rl1, 1);
            rl1 += __shfl_xor_sync(0xffffffffu, rl1, 2);
            l0 = l0 * a0 + rl0;
            l1 = l1 * a1 + rl1;
            m0 = mn0; m1 = mn1;

            __syncwarp();   // Ps visible across lanes of this warp

            // ---- O += P @ V (1x tf32) ----
            #pragma unroll
            for (int ks = 0; ks < 8; ks++) {
                int pc = ks * 8 + q;
                uint32_t a[4];
                a[0] = Ps[(wr + g) * FST + pc];
                a[1] = Ps[(wr + g + 8) * FST + pc];
                a[2] = Ps[(wr + g) * FST + pc + 4];
                a[3] = Ps[(wr + g + 8) * FST + pc + 4];
                #pragma unroll
                for (int nt = 0; nt < 8; nt++) {
                    uint32_t bv[2];
                    bv[0] = Vs[(ks * 8 + q) * VST + nt * 8 + g];
                    bv[1] = Vs[(ks * 8 + q + 4) * VST + nt * 8 + g];
                    mma_tf32(o_acc[nt], a, bv);
                }
            }
        }
        __syncthreads();   // all warps done with K/V before next tile load
    }

    // ---- epilogue ----
    float inv0 = 1.f / l0, inv1 = 1.f / l1;
    float* yp = y + (size_t)(b * T_SEQ + rg0) * 1024 + h * 64;
    #pragma unroll
    for (int nt = 0; nt < 8; nt++) {
        int c = nt * 8 + 2 * q;
        *(float2*)(yp + c) =
            make_float2(o_acc[nt][0] * inv0, o_acc[nt][1] * inv0);
        *(float2*)(yp + (size_t)8 * 1024 + c) =
            make_float2(o_acc[nt][2] * inv1, o_acc[nt][3] * inv1);
    }
}

// ---------------- SiLU(a) * b, in place into a ------------------------------
__global__ __launch_bounds__(256) void silu_mul_k(float* __restrict__ a,
                                                  const float* __restrict__ b,
                                                  int n4) {
    int i = blockIdx.x * 256 + threadIdx.x;
    if (i >= n4) return;
    float4 av = ((float4*)a)[i];
    float4 bv = ((const float4*)b)[i];
    av.x = av.x * bv.x / (1.f + __expf(-av.x));
    av.y = av.y * bv.y / (1.f + __expf(-av.y));
    av.z = av.z * bv.z / (1.f + __expf(-av.z));
    av.w = av.w * bv.w / (1.f + __expf(-av.w));
    ((float4*)a)[i] = av;
}

// ---------------- launch ----------------------------------------------------
#define FLASH_SMEM ((2 * BQ * FST + 2 * BK * FST + BQ * FST + BK * VST) * 4)

extern "C" void kernel_launch(void* const* d_in, const int* in_sizes, int n_in,
                              void* d_out, int out_size) {
    const float* x    = (const float*)d_in[0];
    const int*   ym   = (const int*)  d_in[1];
    const float* Wqkv = (const float*)d_in[2];
    const float* Wap  = (const float*)d_in[3];
    const float* sc1  = (const float*)d_in[4];
    const float* sc2  = (const float*)d_in[5];
    const float* Wfc1 = (const float*)d_in[6];
    const float* Wfc2 = (const float*)d_in[7];
    const float* Wmp  = (const float*)d_in[8];
    float* out = (float*)d_out;

    float *h, *qkv, *y, *x2, *fc1, *fc2;
    cudaGetSymbolAddress((void**)&h,   g_h);
    cudaGetSymbolAddress((void**)&qkv, g_qkv);
    cudaGetSymbolAddress((void**)&y,   g_y);
    cudaGetSymbolAddress((void**)&x2,  g_x2);
    cudaGetSymbolAddress((void**)&fc1, g_fc1);
    cudaGetSymbolAddress((void**)&fc2, g_fc2);

    cudaFuncSetAttribute(flash_mma_k,
                         cudaFuncAttributeMaxDynamicSharedMemorySize,
                         FLASH_SMEM);

    // 1) h = rmsnorm(x, scale1)
    rmsnorm_k<<<TOK, 256>>>(x, sc1, h);
    // 2) qkv = h @ Wqkv
    tf32gemm_k<<<dim3(3072 / 128, TOK / 128), 256>>>(h, Wqkv, qkv, nullptr,
                                                     TOK, 3072, C_EMB);
    // 3) RoPE in place on q,k
    rope_k<<<(1 << 22) / 256, 256>>>(qkv);
    // 4) attention -> y (tensor cores)
    flash_mma_k<<<dim3(T_SEQ / BQ, NHEAD, 2), 256, FLASH_SMEM>>>(qkv, ym, y);
    // 5) x2 = x + y @ Wattn_proj
    tf32gemm_k<<<dim3(C_EMB / 128, TOK / 128), 256>>>(y, Wap, x2, x,
                                                      TOK, C_EMB, C_EMB);
    // 6) h = rmsnorm(x2, scale2)
    rmsnorm_k<<<TOK, 256>>>(x2, sc2, h);
    // 7) fc1 = h @ Wfc1 ; fc2 = h @ Wfc2
    tf32gemm_k<<<dim3(HID / 128, TOK / 128), 256>>>(h, Wfc1, fc1, nullptr,
                                                    TOK, HID, C_EMB);
    tf32gemm_k<<<dim3(HID / 128, TOK / 128), 256>>>(h, Wfc2, fc2, nullptr,
                                                    TOK, HID, C_EMB);
    // 8) fc1 = silu(fc1) * fc2
    int n4 = TOK * HID / 4;
    silu_mul_k<<<(n4 + 255) / 256, 256>>>(fc1, fc2, n4);
    // 9) out = x2 + fc1 @ Wmlp_proj
    tf32gemm_k<<<dim3(C_EMB / 128, TOK / 128), 256>>>(fc1, Wmp, out, x2,
                                                      TOK, C_EMB, HID);
}